// round 11
// baseline (speedup 1.0000x reference)
#include <cuda_runtime.h>
#include <cuda_bf16.h>
#include <cstdint>
#include <cstddef>

#define DK 128
#define NMAX 100000
#define EMAX 640000

// ---------------- scratch (device globals; no allocation allowed) -------------
__device__ float4 g_agg_st4[(size_t)NMAX * (DK / 4)];
__device__ float4 g_agg_ts4[(size_t)NMAX * (DK / 4)];
__device__ int g_deg_in[NMAX];
__device__ int g_deg_out[NMAX];
__device__ int g_off_in[NMAX];
__device__ int g_off_out[NMAX];
__device__ int g_cur_in[NMAX];
__device__ int g_cur_out[NMAX];
__device__ int g_csr_in[EMAX];   // src values grouped by dst
__device__ int g_csr_out[EMAX];  // dst values grouped by src
__device__ float g_inv_in[NMAX];
__device__ float g_inv_out[NMAX];
// Split-bf16 transposed weights: [seg][n][k], 3 x 128 x 128 bf16 = 32KB each half
__device__ uint4 g_Bh4[3 * 2048];
__device__ uint4 g_Bl4[3 * 2048];
__device__ float g_bcomb[DK];

__device__ __forceinline__ uint32_t smem_u32(const void* p) {
    uint32_t a;
    asm("{ .reg .u64 t; cvta.to.shared.u64 t, %1; cvt.u32.u64 %0, t; }" : "=r"(a) : "l"(p));
    return a;
}

// ---------------- CSR build ----------------------------------------------------
__global__ void zero_deg_kernel(int n) {
    int i = blockIdx.x * blockDim.x + threadIdx.x;
    if (i < n) {
        g_deg_in[i] = 0;
        g_deg_out[i] = 0;
    }
}

__global__ void hist_kernel(const int* __restrict__ ei, int E) {
    int e = blockIdx.x * blockDim.x + threadIdx.x;
    if (e >= E) return;
    atomicAdd(g_deg_in + ei[E + e], 1);   // in-degree of dst
    atomicAdd(g_deg_out + ei[e], 1);      // out-degree of src
}

// One block per direction: exclusive prefix scan of degree -> off and cur.
__global__ void __launch_bounds__(1024) scan_kernel(int N) {
    const int* deg = blockIdx.x ? g_deg_out : g_deg_in;
    int* off = blockIdx.x ? g_off_out : g_off_in;
    int* cur = blockIdx.x ? g_cur_out : g_cur_in;
    __shared__ int tsum[1024];
    int t = threadIdx.x;
    int chunk = (N + 1023) >> 10;
    int lo = t * chunk;
    int hi = lo + chunk < N ? lo + chunk : N;
    int s = 0;
    for (int i = lo; i < hi; i++) s += deg[i];
    tsum[t] = s;
    __syncthreads();
    for (int d = 1; d < 1024; d <<= 1) {     // Hillis-Steele inclusive scan
        int v = (t >= d) ? tsum[t - d] : 0;
        __syncthreads();
        tsum[t] += v;
        __syncthreads();
    }
    int pre = (t == 0) ? 0 : tsum[t - 1];    // exclusive base for this chunk
    for (int i = lo; i < hi; i++) {
        off[i] = pre;
        cur[i] = pre;
        pre += deg[i];
    }
}

__global__ void fill_kernel(const int* __restrict__ ei, int E) {
    int e = blockIdx.x * blockDim.x + threadIdx.x;
    if (e >= E) return;
    int s = ei[e], d = ei[E + e];
    int p = atomicAdd(g_cur_in + d, 1);
    g_csr_in[p] = s;
    int q = atomicAdd(g_cur_out + s, 1);
    g_csr_out[q] = d;
}

// Merged: inverse-degree (from int degs) + W transpose/split + combined bias.
__global__ void inv_prep_kernel(int n,
                                const float* __restrict__ Wlin, const float* __restrict__ Wst,
                                const float* __restrict__ Wts, const float* __restrict__ blin,
                                const float* __restrict__ bst, const float* __restrict__ bts) {
    int idx = blockIdx.x * blockDim.x + threadIdx.x;
    if (idx < n) {
        g_inv_in[idx]  = 0.5f / (float)(g_deg_in[idx] > 1 ? g_deg_in[idx] : 1);
        g_inv_out[idx] = 0.5f / (float)(g_deg_out[idx] > 1 ? g_deg_out[idx] : 1);
    }
    if (idx < DK) g_bcomb[idx] = blin[idx] + 0.5f * (bst[idx] + bts[idx]);
    if (idx >= 3 * DK * DK) return;
    int seg = idx >> 14;
    int rem = idx & 16383;
    int nn = rem >> 7, k = rem & 127;
    const float* W = seg == 0 ? Wlin : (seg == 1 ? Wst : Wts);
    float v = W[k * DK + nn];                // B[n][k] = W[k][n]
    __nv_bfloat16 h = __float2bfloat16_rn(v);
    __nv_bfloat16 l = __float2bfloat16_rn(v - __bfloat162float(h));
    ((__nv_bfloat16*)g_Bh4)[idx] = h;
    ((__nv_bfloat16*)g_Bl4)[idx] = l;
}

// One warp per (node, direction): register-accumulate neighbor rows, write once.
// 2-way unroll gives MLP=2 on the dependent gather chain.
__global__ void agg_kernel(const float* __restrict__ x, int N) {
    int gw = (int)((blockIdx.x * (unsigned)blockDim.x + threadIdx.x) >> 5);
    int lane = threadIdx.x & 31;
    if (gw >= 2 * N) return;
    int dir = gw >= N;
    int v = dir ? gw - N : gw;
    int start = dir ? g_off_out[v] : g_off_in[v];
    int deg   = dir ? g_deg_out[v] : g_deg_in[v];
    const int* csr = dir ? g_csr_out : g_csr_in;
    float4 acc = make_float4(0.f, 0.f, 0.f, 0.f);
    int j = start, end = start + deg;
    for (; j + 1 < end; j += 2) {
        int u0 = __ldg(csr + j);
        int u1 = __ldg(csr + j + 1);
        float4 a = __ldg(((const float4*)(x + (size_t)u0 * DK)) + lane);
        float4 b = __ldg(((const float4*)(x + (size_t)u1 * DK)) + lane);
        acc.x += a.x + b.x; acc.y += a.y + b.y;
        acc.z += a.z + b.z; acc.w += a.w + b.w;
    }
    if (j < end) {
        int u = __ldg(csr + j);
        float4 a = __ldg(((const float4*)(x + (size_t)u * DK)) + lane);
        acc.x += a.x; acc.y += a.y; acc.z += a.z; acc.w += a.w;
    }
    float4* dst = dir ? g_agg_ts4 : g_agg_st4;
    dst[(size_t)v * (DK / 4) + lane] = acc;
}

// ---------------- mma.sync split-bf16 GEMM (unchanged R10 winner) --------------
#define MT 64
#define ROWSTR 272
#define SM_AH 0
#define SM_AL 17408
#define SM_BH 34816
#define SM_BL 69632
#define SM_TOT 104448
#define GT 512

#define LDSM4(r0, r1, r2, r3, a) \
    asm volatile("ldmatrix.sync.aligned.m8n8.x4.shared.b16 {%0,%1,%2,%3}, [%4];" \
                 : "=r"(r0), "=r"(r1), "=r"(r2), "=r"(r3) : "r"(a))

#define MMA16816(c, a, b0, b1) \
    asm volatile("mma.sync.aligned.m16n8k16.row.col.f32.bf16.bf16.f32 " \
                 "{%0,%1,%2,%3}, {%4,%5,%6,%7}, {%8,%9}, {%0,%1,%2,%3};" \
                 : "+f"((c)[0]), "+f"((c)[1]), "+f"((c)[2]), "+f"((c)[3]) \
                 : "r"((a)[0]), "r"((a)[1]), "r"((a)[2]), "r"((a)[3]), "r"(b0), "r"(b1))

__global__ void __launch_bounds__(GT, 2) gemm_mma_kernel(
    const float* __restrict__ x, float* __restrict__ out, int N)
{
    extern __shared__ char smem[];
    uint32_t sb = smem_u32(smem);
    int tid = threadIdx.x;
    int wid = tid >> 5;
    int lane = tid & 31;
    int wy = wid >> 3;            // M chunk: rows wy*32 .. +31
    int wxn = wid & 7;            // N chunk: cols wxn*16 .. +15
    int row0 = blockIdx.x * MT;

    float acc[2][2][4];
#pragma unroll
    for (int m = 0; m < 2; m++)
#pragma unroll
        for (int n = 0; n < 2; n++)
#pragma unroll
            for (int q = 0; q < 4; q++) acc[m][n][q] = 0.f;

#pragma unroll 1
    for (int seg = 0; seg < 3; seg++) {
        __syncthreads();
        const uint4* bh = g_Bh4 + seg * 2048;
        const uint4* bl = g_Bl4 + seg * 2048;
#pragma unroll
        for (int i = 0; i < 4; i++) {
            int idx = tid + i * GT;
            int n = idx >> 4, j = idx & 15;
            *(uint4*)(smem + SM_BH + n * ROWSTR + j * 16) = __ldg(bh + idx);
            *(uint4*)(smem + SM_BL + n * ROWSTR + j * 16) = __ldg(bl + idx);
        }
        const float* Asrc = seg == 0 ? x : (seg == 1 ? (const float*)g_agg_st4
                                                     : (const float*)g_agg_ts4);
        const float* inv = (seg == 1) ? g_inv_in : g_inv_out;
#pragma unroll
        for (int i = 0; i < 8; i++) {
            int p = tid + i * GT;
            int r = p >> 6, cp = p & 63;
            int rg = row0 + r;
            float v0 = 0.f, v1 = 0.f;
            if (rg < N) {
                float2 val = __ldg((const float2*)(Asrc + (size_t)rg * DK) + cp);
                float sc = seg ? inv[rg] : 1.0f;
                v0 = val.x * sc;
                v1 = val.y * sc;
            }
            __nv_bfloat162 hp = __floats2bfloat162_rn(v0, v1);
            float h0 = __bfloat162float(__low2bfloat16(hp));
            float h1 = __bfloat162float(__high2bfloat16(hp));
            __nv_bfloat162 lp = __floats2bfloat162_rn(v0 - h0, v1 - h1);
            *(uint32_t*)(smem + SM_AH + r * ROWSTR + cp * 4) = *(uint32_t*)&hp;
            *(uint32_t*)(smem + SM_AL + r * ROWSTR + cp * 4) = *(uint32_t*)&lp;
        }
        __syncthreads();

#pragma unroll 1
        for (int kt = 0; kt < 8; kt++) {
            int nrow = wxn * 16 + (lane & 7) + (lane >> 4) * 8;
            uint32_t b_hi = sb + SM_BH + nrow * ROWSTR + kt * 32 + ((lane >> 3) & 1) * 16;
            uint32_t bh0, bh1, bh2, bh3, bl0, bl1, bl2, bl3;
            LDSM4(bh0, bh1, bh2, bh3, b_hi);
            LDSM4(bl0, bl1, bl2, bl3, b_hi + (SM_BL - SM_BH));
#pragma unroll
            for (int mt = 0; mt < 2; mt++) {
                int row = wy * 32 + mt * 16 + (lane & 7) + ((lane >> 3) & 1) * 8;
                uint32_t a_hi = sb + SM_AH + row * ROWSTR + kt * 32 + (lane >> 4) * 16;
                uint32_t ah[4], al[4];
                LDSM4(ah[0], ah[1], ah[2], ah[3], a_hi);
                LDSM4(al[0], al[1], al[2], al[3], a_hi + (SM_AL - SM_AH));
                MMA16816(acc[mt][0], ah, bh0, bh1);
                MMA16816(acc[mt][0], ah, bl0, bl1);
                MMA16816(acc[mt][0], al, bh0, bh1);
                MMA16816(acc[mt][1], ah, bh2, bh3);
                MMA16816(acc[mt][1], ah, bl2, bl3);
                MMA16816(acc[mt][1], al, bh2, bh3);
            }
        }
    }

#pragma unroll
    for (int mt = 0; mt < 2; mt++) {
        int rbase = row0 + wy * 32 + mt * 16 + (lane >> 2);
#pragma unroll
        for (int dd = 0; dd < 2; dd++) {
            int rg = rbase + dd * 8;
            if (rg < N) {
                float* orow = out + (size_t)rg * DK;
#pragma unroll
                for (int nt = 0; nt < 2; nt++) {
                    int c = wxn * 16 + nt * 8 + (lane & 3) * 2;
                    float2 bb = *(const float2*)(g_bcomb + c);
                    float2 o;
                    o.x = acc[mt][nt][dd * 2 + 0] + bb.x;
                    o.y = acc[mt][nt][dd * 2 + 1] + bb.y;
                    *(float2*)(orow + c) = o;
                }
            }
        }
    }
}

// ---------------- host launch --------------------------------------------------
extern "C" void kernel_launch(void* const* d_in, const int* in_sizes, int n_in,
                              void* d_out, int out_size) {
    const float* x    = (const float*)d_in[0];
    const int*   ei   = (const int*)d_in[1];      // int32
    const float* Wlin = (const float*)d_in[2];
    const float* blin = (const float*)d_in[3];
    const float* Wst  = (const float*)d_in[4];
    const float* bst  = (const float*)d_in[5];
    const float* Wts  = (const float*)d_in[6];
    const float* bts  = (const float*)d_in[7];
    float* out = (float*)d_out;
    int N = in_sizes[0] / DK;
    int E = in_sizes[1] / 2;

    zero_deg_kernel<<<(N + 255) / 256, 256>>>(N);
    hist_kernel<<<(E + 255) / 256, 256>>>(ei, E);
    scan_kernel<<<2, 1024>>>(N);
    fill_kernel<<<(E + 255) / 256, 256>>>(ei, E);

    int ip_n = (3 * DK * DK > NMAX) ? 3 * DK * DK : NMAX;
    inv_prep_kernel<<<(ip_n + 255) / 256, 256>>>(N, Wlin, Wst, Wts, blin, bst, bts);

    long long aggw = (long long)2 * N * 32;
    agg_kernel<<<(int)((aggw + 255) / 256), 256>>>(x, N);

    cudaFuncSetAttribute(gemm_mma_kernel, cudaFuncAttributeMaxDynamicSharedMemorySize, SM_TOT);
    gemm_mma_kernel<<<(N + MT - 1) / MT, GT, SM_TOT>>>(x, out, N);
}

// round 13
// speedup vs baseline: 1.2647x; 1.2647x over previous
#include <cuda_runtime.h>
#include <cuda_bf16.h>
#include <cstdint>
#include <cstddef>

#define DK 128
#define NMAX 100000

// ---------------- scratch (device globals; no allocation allowed) -------------
__device__ float4 g_agg_st4[(size_t)NMAX * (DK / 4)];
__device__ float4 g_agg_ts4[(size_t)NMAX * (DK / 4)];
__device__ float g_cnt_in[NMAX];
__device__ float g_cnt_out[NMAX];
__device__ float g_inv_in[NMAX];
__device__ float g_inv_out[NMAX];
// Split-bf16 transposed weights: [seg][n][k], 3 x 128 x 128 bf16 = 32KB each half
__device__ uint4 g_Bh4[3 * 2048];
__device__ uint4 g_Bl4[3 * 2048];
__device__ float g_bcomb[DK];

__device__ __forceinline__ uint32_t smem_u32(const void* p) {
    uint32_t a;
    asm("{ .reg .u64 t; cvta.to.shared.u64 t, %1; cvt.u32.u64 %0, t; }" : "=r"(a) : "l"(p));
    return a;
}

// ---------------- phase kernels ----------------------------------------------
__global__ void zero_kernel(int n_nodes) {
    int stride = gridDim.x * blockDim.x;
    int i0 = blockIdx.x * blockDim.x + threadIdx.x;
    int total4 = n_nodes * (DK / 4);
    float4 z = make_float4(0.f, 0.f, 0.f, 0.f);
    for (int i = i0; i < total4; i += stride) {
        g_agg_st4[i] = z;
        g_agg_ts4[i] = z;
    }
    for (int i = i0; i < n_nodes; i += stride) {
        g_cnt_in[i] = 0.f;
        g_cnt_out[i] = 0.f;
    }
}

// One warp per edge, both directions. edge_index is int32. This kernel runs at
// the LTS byte cap (1.31GB through L2 ~= 130us) — throughput-optimal for this
// traffic pattern (R11's CSR variant regressed; reverted).
__global__ void scatter_kernel(const float* __restrict__ x,
                               const int* __restrict__ ei, int E) {
    int e = (int)((blockIdx.x * (unsigned)blockDim.x + threadIdx.x) >> 5);
    int lane = threadIdx.x & 31;
    if (e >= E) return;
    int s = ei[e];
    int d = ei[E + e];
    float4 vs = __ldg(((const float4*)(x + (size_t)s * DK)) + lane);
    float4 vd = __ldg(((const float4*)(x + (size_t)d * DK)) + lane);
    float4* pst = g_agg_st4 + (size_t)d * (DK / 4) + lane;
    float4* pts = g_agg_ts4 + (size_t)s * (DK / 4) + lane;
    asm volatile("red.global.add.v4.f32 [%0], {%1, %2, %3, %4};"
                 :: "l"(pst), "f"(vs.x), "f"(vs.y), "f"(vs.z), "f"(vs.w) : "memory");
    asm volatile("red.global.add.v4.f32 [%0], {%1, %2, %3, %4};"
                 :: "l"(pts), "f"(vd.x), "f"(vd.y), "f"(vd.z), "f"(vd.w) : "memory");
    if (lane == 0) {
        atomicAdd(g_cnt_in + d, 1.0f);
        atomicAdd(g_cnt_out + s, 1.0f);
    }
}

// Merged: inverse-degree + W transpose/split + combined bias.
__global__ void inv_prep_kernel(int n,
                                const float* __restrict__ Wlin, const float* __restrict__ Wst,
                                const float* __restrict__ Wts, const float* __restrict__ blin,
                                const float* __restrict__ bst, const float* __restrict__ bts) {
    int idx = blockIdx.x * blockDim.x + threadIdx.x;
    if (idx < n) {
        g_inv_in[idx]  = 0.5f / fmaxf(g_cnt_in[idx], 1.f);
        g_inv_out[idx] = 0.5f / fmaxf(g_cnt_out[idx], 1.f);
    }
    if (idx < DK) g_bcomb[idx] = blin[idx] + 0.5f * (bst[idx] + bts[idx]);
    if (idx >= 3 * DK * DK) return;
    int seg = idx >> 14;
    int rem = idx & 16383;
    int nn = rem >> 7, k = rem & 127;
    const float* W = seg == 0 ? Wlin : (seg == 1 ? Wst : Wts);
    float v = W[k * DK + nn];                // B[n][k] = W[k][n]
    __nv_bfloat16 h = __float2bfloat16_rn(v);
    __nv_bfloat16 l = __float2bfloat16_rn(v - __bfloat162float(h));
    ((__nv_bfloat16*)g_Bh4)[idx] = h;
    ((__nv_bfloat16*)g_Bl4)[idx] = l;
}

// ---------------- mma.sync split-bf16 GEMM ------------------------------------
// Per CTA: 64 rows x 128 cols; K = 3 segments x 128. 512 threads = 16 warps,
// warp grid 2(M) x 8(N). smem 102KB -> 2 CTAs/SM (occ 50%), 64-reg cap.
// R12: all 6 LDSM hoisted ahead of the 12 MMAs per kt -> 4 independent
// 3-deep MMA chains with operands ready (ILP up vs R10's interleaved loads).
#define MT 64
#define ROWSTR 272
#define SM_AH 0
#define SM_AL 17408
#define SM_BH 34816
#define SM_BL 69632
#define SM_TOT 104448
#define GT 512

#define LDSM4(r0, r1, r2, r3, a) \
    asm volatile("ldmatrix.sync.aligned.m8n8.x4.shared.b16 {%0,%1,%2,%3}, [%4];" \
                 : "=r"(r0), "=r"(r1), "=r"(r2), "=r"(r3) : "r"(a))

#define MMA16816(c, a, b0, b1) \
    asm volatile("mma.sync.aligned.m16n8k16.row.col.f32.bf16.bf16.f32 " \
                 "{%0,%1,%2,%3}, {%4,%5,%6,%7}, {%8,%9}, {%0,%1,%2,%3};" \
                 : "+f"((c)[0]), "+f"((c)[1]), "+f"((c)[2]), "+f"((c)[3]) \
                 : "r"((a)[0]), "r"((a)[1]), "r"((a)[2]), "r"((a)[3]), "r"(b0), "r"(b1))

__global__ void __launch_bounds__(GT, 2) gemm_mma_kernel(
    const float* __restrict__ x, float* __restrict__ out, int N)
{
    extern __shared__ char smem[];
    uint32_t sb = smem_u32(smem);
    int tid = threadIdx.x;
    int wid = tid >> 5;
    int lane = tid & 31;
    int wy = wid >> 3;            // M chunk: rows wy*32 .. +31
    int wxn = wid & 7;            // N chunk: cols wxn*16 .. +15
    int row0 = blockIdx.x * MT;

    float acc[2][2][4];
#pragma unroll
    for (int m = 0; m < 2; m++)
#pragma unroll
        for (int n = 0; n < 2; n++)
#pragma unroll
            for (int q = 0; q < 4; q++) acc[m][n][q] = 0.f;

#pragma unroll 1
    for (int seg = 0; seg < 3; seg++) {
        __syncthreads();
        const uint4* bh = g_Bh4 + seg * 2048;
        const uint4* bl = g_Bl4 + seg * 2048;
#pragma unroll
        for (int i = 0; i < 4; i++) {
            int idx = tid + i * GT;
            int n = idx >> 4, j = idx & 15;
            *(uint4*)(smem + SM_BH + n * ROWSTR + j * 16) = __ldg(bh + idx);
            *(uint4*)(smem + SM_BL + n * ROWSTR + j * 16) = __ldg(bl + idx);
        }
        const float* Asrc = seg == 0 ? x : (seg == 1 ? (const float*)g_agg_st4
                                                     : (const float*)g_agg_ts4);
        const float* inv = (seg == 1) ? g_inv_in : g_inv_out;
#pragma unroll
        for (int i = 0; i < 8; i++) {
            int p = tid + i * GT;
            int r = p >> 6, cp = p & 63;
            int rg = row0 + r;
            float v0 = 0.f, v1 = 0.f;
            if (rg < N) {
                float2 val = __ldg((const float2*)(Asrc + (size_t)rg * DK) + cp);
                float sc = seg ? inv[rg] : 1.0f;
                v0 = val.x * sc;
                v1 = val.y * sc;
            }
            __nv_bfloat162 hp = __floats2bfloat162_rn(v0, v1);
            float h0 = __bfloat162float(__low2bfloat16(hp));
            float h1 = __bfloat162float(__high2bfloat16(hp));
            __nv_bfloat162 lp = __floats2bfloat162_rn(v0 - h0, v1 - h1);
            *(uint32_t*)(smem + SM_AH + r * ROWSTR + cp * 4) = *(uint32_t*)&hp;
            *(uint32_t*)(smem + SM_AL + r * ROWSTR + cp * 4) = *(uint32_t*)&lp;
        }
        __syncthreads();

#pragma unroll 1
        for (int kt = 0; kt < 8; kt++) {
            // ---- all loads first ----
            int nrow = wxn * 16 + (lane & 7) + (lane >> 4) * 8;
            uint32_t b_hi = sb + SM_BH + nrow * ROWSTR + kt * 32 + ((lane >> 3) & 1) * 16;
            uint32_t bh0, bh1, bh2, bh3, bl0, bl1, bl2, bl3;
            LDSM4(bh0, bh1, bh2, bh3, b_hi);
            LDSM4(bl0, bl1, bl2, bl3, b_hi + (SM_BL - SM_BH));
            int rowa = wy * 32 + (lane & 7) + ((lane >> 3) & 1) * 8;
            uint32_t a0 = sb + SM_AH + rowa * ROWSTR + kt * 32 + (lane >> 4) * 16;
            uint32_t ah0[4], al0[4], ah1[4], al1[4];
            LDSM4(ah0[0], ah0[1], ah0[2], ah0[3], a0);
            LDSM4(al0[0], al0[1], al0[2], al0[3], a0 + (SM_AL - SM_AH));
            uint32_t a1 = a0 + 16 * ROWSTR;
            LDSM4(ah1[0], ah1[1], ah1[2], ah1[3], a1);
            LDSM4(al1[0], al1[1], al1[2], al1[3], a1 + (SM_AL - SM_AH));
            // ---- 12 MMAs: 4 independent acc chains of depth 3 ----
            MMA16816(acc[0][0], ah0, bh0, bh1);
            MMA16816(acc[0][1], ah0, bh2, bh3);
            MMA16816(acc[1][0], ah1, bh0, bh1);
            MMA16816(acc[1][1], ah1, bh2, bh3);
            MMA16816(acc[0][0], ah0, bl0, bl1);
            MMA16816(acc[0][1], ah0, bl2, bl3);
            MMA16816(acc[1][0], ah1, bl0, bl1);
            MMA16816(acc[1][1], ah1, bl2, bl3);
            MMA16816(acc[0][0], al0, bh0, bh1);
            MMA16816(acc[0][1], al0, bh2, bh3);
            MMA16816(acc[1][0], al1, bh0, bh1);
            MMA16816(acc[1][1], al1, bh2, bh3);
        }
    }

#pragma unroll
    for (int mt = 0; mt < 2; mt++) {
        int rbase = row0 + wy * 32 + mt * 16 + (lane >> 2);
#pragma unroll
        for (int dd = 0; dd < 2; dd++) {
            int rg = rbase + dd * 8;
            if (rg < N) {
                float* orow = out + (size_t)rg * DK;
#pragma unroll
                for (int nt = 0; nt < 2; nt++) {
                    int c = wxn * 16 + nt * 8 + (lane & 3) * 2;
                    float2 bb = *(const float2*)(g_bcomb + c);
                    float2 o;
                    o.x = acc[mt][nt][dd * 2 + 0] + bb.x;
                    o.y = acc[mt][nt][dd * 2 + 1] + bb.y;
                    *(float2*)(orow + c) = o;
                }
            }
        }
    }
}

// ---------------- host launch --------------------------------------------------
extern "C" void kernel_launch(void* const* d_in, const int* in_sizes, int n_in,
                              void* d_out, int out_size) {
    const float* x    = (const float*)d_in[0];
    const int*   ei   = (const int*)d_in[1];      // int32
    const float* Wlin = (const float*)d_in[2];
    const float* blin = (const float*)d_in[3];
    const float* Wst  = (const float*)d_in[4];
    const float* bst  = (const float*)d_in[5];
    const float* Wts  = (const float*)d_in[6];
    const float* bts  = (const float*)d_in[7];
    float* out = (float*)d_out;
    int N = in_sizes[0] / DK;
    int E = in_sizes[1] / 2;

    zero_kernel<<<1024, 256>>>(N);

    long long total_threads = (long long)E * 32;
    int blocks = (int)((total_threads + 255) / 256);
    scatter_kernel<<<blocks, 256>>>(x, ei, E);

    int ip_n = (3 * DK * DK > NMAX) ? 3 * DK * DK : NMAX;
    inv_prep_kernel<<<(ip_n + 255) / 256, 256>>>(N, Wlin, Wst, Wts, blin, bst, bts);

    cudaFuncSetAttribute(gemm_mma_kernel, cudaFuncAttributeMaxDynamicSharedMemorySize, SM_TOT);
    gemm_mma_kernel<<<(N + MT - 1) / MT, GT, SM_TOT>>>(x, out, N);
}

// round 17
// speedup vs baseline: 1.3929x; 1.1014x over previous
#include <cuda_runtime.h>
#include <cuda_fp16.h>
#include <cstdint>
#include <cstddef>

#define DK 128
#define NMAX 100000

// ---------------- scratch (device globals; no allocation allowed) -------------
__device__ float4 g_agg_st4[(size_t)NMAX * (DK / 4)];
__device__ float4 g_agg_ts4[(size_t)NMAX * (DK / 4)];
__device__ float g_cnt_in[NMAX];
__device__ float g_cnt_out[NMAX];
__device__ float g_inv_in[NMAX];
__device__ float g_inv_out[NMAX];
// fp16 transposed weights: [seg][n][k], 3 x 128 x 128 fp16 = 32KB each
__device__ uint4 g_Bh4[3 * 2048];
__device__ float g_bcomb[DK];

__device__ __forceinline__ uint32_t smem_u32(const void* p) {
    uint32_t a;
    asm("{ .reg .u64 t; cvta.to.shared.u64 t, %1; cvt.u32.u64 %0, t; }" : "=r"(a) : "l"(p));
    return a;
}

// ---------------- phase kernels ----------------------------------------------
__global__ void zero_kernel(int n_nodes) {
    int stride = gridDim.x * blockDim.x;
    int i0 = blockIdx.x * blockDim.x + threadIdx.x;
    int total4 = n_nodes * (DK / 4);
    float4 z = make_float4(0.f, 0.f, 0.f, 0.f);
    for (int i = i0; i < total4; i += stride) {
        g_agg_st4[i] = z;
        g_agg_ts4[i] = z;
    }
    for (int i = i0; i < n_nodes; i += stride) {
        g_cnt_in[i] = 0.f;
        g_cnt_out[i] = 0.f;
    }
}

// One warp per edge, both directions. edge_index is int32. Runs at the LTS
// byte cap (1.31GB through L2 ~= 130us) — throughput-optimal for this pattern.
__global__ void scatter_kernel(const float* __restrict__ x,
                               const int* __restrict__ ei, int E) {
    int e = (int)((blockIdx.x * (unsigned)blockDim.x + threadIdx.x) >> 5);
    int lane = threadIdx.x & 31;
    if (e >= E) return;
    int s = ei[e];
    int d = ei[E + e];
    float4 vs = __ldg(((const float4*)(x + (size_t)s * DK)) + lane);
    float4 vd = __ldg(((const float4*)(x + (size_t)d * DK)) + lane);
    float4* pst = g_agg_st4 + (size_t)d * (DK / 4) + lane;
    float4* pts = g_agg_ts4 + (size_t)s * (DK / 4) + lane;
    asm volatile("red.global.add.v4.f32 [%0], {%1, %2, %3, %4};"
                 :: "l"(pst), "f"(vs.x), "f"(vs.y), "f"(vs.z), "f"(vs.w) : "memory");
    asm volatile("red.global.add.v4.f32 [%0], {%1, %2, %3, %4};"
                 :: "l"(pts), "f"(vd.x), "f"(vd.y), "f"(vd.z), "f"(vd.w) : "memory");
    if (lane == 0) {
        atomicAdd(g_cnt_in + d, 1.0f);
        atomicAdd(g_cnt_out + s, 1.0f);
    }
}

// Merged: inverse-degree + W transpose to fp16 [n][k] + combined bias.
__global__ void inv_prep_kernel(int n,
                                const float* __restrict__ Wlin, const float* __restrict__ Wst,
                                const float* __restrict__ Wts, const float* __restrict__ blin,
                                const float* __restrict__ bst, const float* __restrict__ bts) {
    int idx = blockIdx.x * blockDim.x + threadIdx.x;
    if (idx < n) {
        g_inv_in[idx]  = 0.5f / fmaxf(g_cnt_in[idx], 1.f);
        g_inv_out[idx] = 0.5f / fmaxf(g_cnt_out[idx], 1.f);
    }
    if (idx < DK) g_bcomb[idx] = blin[idx] + 0.5f * (bst[idx] + bts[idx]);
    if (idx >= 3 * DK * DK) return;
    int seg = idx >> 14;
    int rem = idx & 16383;
    int nn = rem >> 7, k = rem & 127;
    const float* W = seg == 0 ? Wlin : (seg == 1 ? Wst : Wts);
    float v = W[k * DK + nn];                // B[n][k] = W[k][n]
    ((__half*)g_Bh4)[idx] = __float2half_rn(v);
}

// ---------------- mma.sync fp16 GEMM ------------------------------------------
// Per CTA: 64 rows x 128 cols; K = 3 segments x 128. 512 threads = 16 warps,
// warp grid 2(M) x 8(N). Single fp16 term (no split): error ~2^-11.5 * sqrt(2)
// ~ 3.5e-4 << 1e-3. smem 52KB. Per kt: 3 LDSM + 4 MMA.
#define MT 64
#define ROWSTR 272
#define SM_AH 0
#define SM_BH 17408
#define SM_TOT 52224
#define GT 512

#define LDSM4(r0, r1, r2, r3, a) \
    asm volatile("ldmatrix.sync.aligned.m8n8.x4.shared.b16 {%0,%1,%2,%3}, [%4];" \
                 : "=r"(r0), "=r"(r1), "=r"(r2), "=r"(r3) : "r"(a))

#define MMA16816(c, a, b0, b1) \
    asm volatile("mma.sync.aligned.m16n8k16.row.col.f32.f16.f16.f32 " \
                 "{%0,%1,%2,%3}, {%4,%5,%6,%7}, {%8,%9}, {%0,%1,%2,%3};" \
                 : "+f"((c)[0]), "+f"((c)[1]), "+f"((c)[2]), "+f"((c)[3]) \
                 : "r"((a)[0]), "r"((a)[1]), "r"((a)[2]), "r"((a)[3]), "r"(b0), "r"(b1))

__global__ void __launch_bounds__(GT, 2) gemm_mma_kernel(
    const float* __restrict__ x, float* __restrict__ out, int N)
{
    extern __shared__ char smem[];
    uint32_t sb = smem_u32(smem);
    int tid = threadIdx.x;
    int wid = tid >> 5;
    int lane = tid & 31;
    int wy = wid >> 3;            // M chunk: rows wy*32 .. +31
    int wxn = wid & 7;            // N chunk: cols wxn*16 .. +15
    int row0 = blockIdx.x * MT;

    float acc[2][2][4];
#pragma unroll
    for (int m = 0; m < 2; m++)
#pragma unroll
        for (int n = 0; n < 2; n++)
#pragma unroll
            for (int q = 0; q < 4; q++) acc[m][n][q] = 0.f;

#pragma unroll 1
    for (int seg = 0; seg < 3; seg++) {
        __syncthreads();
        // --- stage B: 32KB fp16 [128 n-rows][128 k], padded rows ---
        const uint4* bh = g_Bh4 + seg * 2048;
#pragma unroll
        for (int i = 0; i < 4; i++) {
            int idx = tid + i * GT;
            int n = idx >> 4, j = idx & 15;
            *(uint4*)(smem + SM_BH + n * ROWSTR + j * 16) = __ldg(bh + idx);
        }
        // --- stage A: f32 -> fp16, inv folded (64 rows x 64 float2) ---
        const float* Asrc = seg == 0 ? x : (seg == 1 ? (const float*)g_agg_st4
                                                     : (const float*)g_agg_ts4);
        const float* inv = (seg == 1) ? g_inv_in : g_inv_out;
#pragma unroll
        for (int i = 0; i < 8; i++) {
            int p = tid + i * GT;
            int r = p >> 6, cp = p & 63;
            int rg = row0 + r;
            float2 v = make_float2(0.f, 0.f);
            if (rg < N) {
                v = __ldg((const float2*)(Asrc + (size_t)rg * DK) + cp);
                if (seg) {
                    float sc = inv[rg];
                    v.x *= sc; v.y *= sc;
                }
            }
            __half2 hp = __float22half2_rn(v);
            *(uint32_t*)(smem + SM_AH + r * ROWSTR + cp * 4) = *(uint32_t*)&hp;
        }
        __syncthreads();

        // --- mainloop: 8 k-tiles x (2 m-tiles x 2 n8-pairs) ---
#pragma unroll 1
        for (int kt = 0; kt < 8; kt++) {
            int nrow = wxn * 16 + (lane & 7) + (lane >> 4) * 8;
            uint32_t b_ad = sb + SM_BH + nrow * ROWSTR + kt * 32 + ((lane >> 3) & 1) * 16;
            uint32_t b0, b1, b2, b3;
            LDSM4(b0, b1, b2, b3, b_ad);
            int rowa = wy * 32 + (lane & 7) + ((lane >> 3) & 1) * 8;
            uint32_t a_ad = sb + SM_AH + rowa * ROWSTR + kt * 32 + (lane >> 4) * 16;
            uint32_t a0[4], a1[4];
            LDSM4(a0[0], a0[1], a0[2], a0[3], a_ad);
            LDSM4(a1[0], a1[1], a1[2], a1[3], a_ad + 16 * ROWSTR);
            MMA16816(acc[0][0], a0, b0, b1);
            MMA16816(acc[0][1], a0, b2, b3);
            MMA16816(acc[1][0], a1, b0, b1);
            MMA16816(acc[1][1], a1, b2, b3);
        }
    }

    // --- epilogue: bias + store ---
#pragma unroll
    for (int mt = 0; mt < 2; mt++) {
        int rbase = row0 + wy * 32 + mt * 16 + (lane >> 2);
#pragma unroll
        for (int dd = 0; dd < 2; dd++) {
            int rg = rbase + dd * 8;
            if (rg < N) {
                float* orow = out + (size_t)rg * DK;
#pragma unroll
                for (int nt = 0; nt < 2; nt++) {
                    int c = wxn * 16 + nt * 8 + (lane & 3) * 2;
                    float2 bb = *(const float2*)(g_bcomb + c);
                    float2 o;
                    o.x = acc[mt][nt][dd * 2 + 0] + bb.x;
                    o.y = acc[mt][nt][dd * 2 + 1] + bb.y;
                    *(float2*)(orow + c) = o;
                }
            }
        }
    }
}

// ---------------- host launch --------------------------------------------------
extern "C" void kernel_launch(void* const* d_in, const int* in_sizes, int n_in,
                              void* d_out, int out_size) {
    const float* x    = (const float*)d_in[0];
    const int*   ei   = (const int*)d_in[1];      // int32
    const float* Wlin = (const float*)d_in[2];
    const float* blin = (const float*)d_in[3];
    const float* Wst  = (const float*)d_in[4];
    const float* bst  = (const float*)d_in[5];
    const float* Wts  = (const float*)d_in[6];
    const float* bts  = (const float*)d_in[7];
    float* out = (float*)d_out;
    int N = in_sizes[0] / DK;
    int E = in_sizes[1] / 2;

    zero_kernel<<<1024, 256>>>(N);

    long long total_threads = (long long)E * 32;
    int blocks = (int)((total_threads + 255) / 256);
    scatter_kernel<<<blocks, 256>>>(x, ei, E);

    int ip_n = (3 * DK * DK > NMAX) ? 3 * DK * DK : NMAX;
    inv_prep_kernel<<<(ip_n + 255) / 256, 256>>>(N, Wlin, Wst, Wts, blin, bst, bts);

    cudaFuncSetAttribute(gemm_mma_kernel, cudaFuncAttributeMaxDynamicSharedMemorySize, SM_TOT);
    gemm_mma_kernel<<<(N + MT - 1) / MT, GT, SM_TOT>>>(x, out, N);
}